// round 8
// baseline (speedup 1.0000x reference)
#include <cuda_runtime.h>
#include <cuda_bf16.h>
#include <cstdint>

#define GRID_N 64
#define NSAMP 128
#define HDIM 64
#define NRAY_MAX 8192
#define NSAMP_TOT (NRAY_MAX * NSAMP)

#define AMINX (-1.25f)
#define AMINY (-1.55f)
#define AMINZ (-1.25f)
#define SCALE (2.5f)

// ---- scratch (device globals) ----
__device__ float4   g_list[NSAMP_TOT];
__device__ float4   g_rgbsig[NSAMP_TOT];
__device__ unsigned g_maskbits[NRAY_MAX * 4];
__device__ int      g_count;

#define FFMA2(acc, a, b) \
    asm("fma.rn.f32x2 %0, %1, %2, %0;" : "+l"(acc) : "l"(a), "l"(b))
#define PACK2(out, lo, hi) \
    asm("mov.b64 %0, {%1, %2};" : "=l"(out) : "f"(lo), "f"(hi))
#define UNPACK2(lo, hi, in) \
    asm("mov.b64 {%0, %1}, %2;" : "=f"(lo), "=f"(hi) : "l"(in))

// ============================================================
// K1: sampling + occupancy mask + global compaction (bit-exact)
// ============================================================
__global__ __launch_bounds__(512) void k1_sample(
    const float* __restrict__ rays_o, const float* __restrict__ rays_d,
    const float* __restrict__ near_, const float* __restrict__ far_,
    const float* __restrict__ jitter, const float* __restrict__ density,
    int N)
{
    __shared__ int warpcnt[16];
    __shared__ int base_s;

    const int tid  = threadIdx.x;
    const int w    = tid >> 5;
    const int lane = tid & 31;
    const int r    = tid >> 7;
    const int s    = tid & 127;
    const int n    = blockIdx.x * 4 + r;
    const bool valid = (n < N);

    bool mask = false;
    float px = 0.f, py = 0.f, pz = 0.f;

    if (valid) {
        const float ox = rays_o[3 * n + 0], oy = rays_o[3 * n + 1], oz = rays_o[3 * n + 2];
        const float dx = rays_d[3 * n + 0], dy = rays_d[3 * n + 1], dz = rays_d[3 * n + 2];
        const float nr = near_[n], fr = far_[n];
        const float step = __fmul_rn(__fsub_rn(fr, nr), 0.0078125f);

        float z = __fadd_rn(nr, __fmul_rn((float)s, step));
        float p0x = __fadd_rn(ox, __fmul_rn(z, dx));
        float p0y = __fadd_rn(oy, __fmul_rn(z, dy));
        float p0z = __fadd_rn(oz, __fmul_rn(z, dz));
        float ux = __fmul_rn(__fdiv_rn(__fsub_rn(p0x, AMINX), SCALE), (float)GRID_N);
        float uy = __fmul_rn(__fdiv_rn(__fsub_rn(p0y, AMINY), SCALE), (float)GRID_N);
        float uz = __fmul_rn(__fdiv_rn(__fsub_rn(p0z, AMINZ), SCALE), (float)GRID_N);
        int ix = (int)floorf(ux);
        int iy = (int)floorf(uy);
        int iz = (int)floorf(uz);
        bool inb = (ix >= 0) & (ix < GRID_N) & (iy >= 0) & (iy < GRID_N)
                 & (iz >= 0) & (iz < GRID_N);
        if (inb) {
            float dv = density[(ix << 12) + (iy << 6) + iz];
            mask = dv > 0.5f;
        }
        float zbase = mask ? z : 0.0f;
        float jit = jitter[n * NSAMP + s];
        float zv = __fadd_rn(zbase, __fmul_rn(jit, step));
        px = __fadd_rn(ox, __fmul_rn(zv, dx));
        py = __fadd_rn(oy, __fmul_rn(zv, dy));
        pz = __fadd_rn(oz, __fmul_rn(zv, dz));
    }

    unsigned bal = __ballot_sync(0xffffffffu, mask);
    int pre = __popc(bal & ((1u << lane) - 1u));
    if (lane == 0) {
        warpcnt[w] = __popc(bal);
        if (valid) g_maskbits[n * 4 + (w & 3)] = bal;
    }
    __syncthreads();
    if (tid == 0) {
        int total = 0;
        #pragma unroll
        for (int i = 0; i < 16; i++) total += warpcnt[i];
        base_s = atomicAdd(&g_count, total);
    }
    int wbase = 0;
    #pragma unroll
    for (int i = 0; i < 16; i++) if (i < w) wbase += warpcnt[i];
    __syncthreads();

    if (mask) {
        int pos = base_s + wbase + pre;
        g_list[pos] = make_float4(px, py, pz, __int_as_float(n * NSAMP + s));
    }
}

// ============================================================
// K2: register-tiled FFMA2 GEMM, 128-sample tiles
//   dyn smem: A[64][128] f32 (k-major layer1 output)   32KB
//             Bdup[64][64] ull ({w,w} duplicated W2)   32KB
//   thread tile: 8 samples x 8 cols, acc = f32x2 over sample pairs
// ============================================================
#define DYN_SMEM 65536

__global__ __launch_bounds__(128, 2) void k2_mlp(
    const float* __restrict__ W1, const float* __restrict__ b1,
    const float* __restrict__ W2, const float* __restrict__ b2,
    const float* __restrict__ Wsig, const float* __restrict__ bsig,
    const float* __restrict__ Wrgb, const float* __restrict__ brgb)
{
    extern __shared__ __align__(16) char dyn[];
    float* A = (float*)dyn;                                            // A[k*128 + s]
    unsigned long long* Bd = (unsigned long long*)(dyn + 32768);       // Bd[k*64 + c]

    __shared__ float  W1s[3 * HDIM];
    __shared__ float  b1s[HDIM];
    __shared__ float  b2s[HDIM];
    __shared__ float4 Wos[HDIM];
    __shared__ float  bias4[4];
    __shared__ int    ids_s[128];

    const int tid = threadIdx.x;

    // ---- stage weights ----
    for (int i = tid; i < 3 * HDIM; i += 128) W1s[i] = W1[i];
    if (tid < HDIM) {
        b1s[tid] = b1[tid];
        b2s[tid] = b2[tid];
        Wos[tid] = make_float4(Wrgb[3 * tid + 0], Wrgb[3 * tid + 1],
                               Wrgb[3 * tid + 2], Wsig[tid]);
    }
    if (tid < 3) bias4[tid] = brgb[tid];
    if (tid == 3) bias4[3] = bsig[0];

    // Bdup[k][c] = {W2[k][c], W2[k][c]}  (h2[c] = sum_k h1[k]*W2[k*64+c])
    #pragma unroll 4
    for (int i = tid; i < HDIM * HDIM; i += 128) {
        float wv = W2[i];
        unsigned long long p;
        PACK2(p, wv, wv);
        Bd[i] = p;
    }
    __syncthreads();

    const int total  = g_count;
    const int ntiles = (total + 127) >> 7;
    const int sg = tid >> 3;          // 0..15  sample group
    const int cg = tid & 7;           // 0..7   col group
    const int s0 = sg << 3;
    const int c0 = cg << 3;

    for (int t = blockIdx.x; t < ntiles; t += gridDim.x) {
        // ---- layer 1: one sample per thread, store k-major ----
        const int i = (t << 7) + tid;
        const bool live = (i < total);
        float px = 0.f, py = 0.f, pz = 0.f;
        int id = -1;
        if (live) {
            float4 e = g_list[i];
            px = e.x; py = e.y; pz = e.z;
            id = __float_as_int(e.w);
        }
        ids_s[tid] = id;
        #pragma unroll
        for (int k = 0; k < HDIM; k++) {
            float a = fmaf(px, W1s[k], fmaf(py, W1s[HDIM + k], fmaf(pz, W1s[2 * HDIM + k], b1s[k])));
            A[k * 128 + tid] = fmaxf(a, 0.0f);
        }
        __syncthreads();

        // ---- GEMM: acc[sp][c] over k, f32x2 packs sample pairs ----
        unsigned long long acc[4][8];
        #pragma unroll
        for (int c = 0; c < 8; c++) {
            float bv = b2s[c0 + c];
            unsigned long long p;
            PACK2(p, bv, bv);
            acc[0][c] = p; acc[1][c] = p; acc[2][c] = p; acc[3][c] = p;
        }
        #pragma unroll 4
        for (int k = 0; k < HDIM; k++) {
            const ulonglong2* ap = reinterpret_cast<const ulonglong2*>(&A[k * 128 + s0]);
            const ulonglong2* bp = reinterpret_cast<const ulonglong2*>(&Bd[k * 64 + c0]);
            ulonglong2 a01 = ap[0], a23 = ap[1];
            ulonglong2 b01 = bp[0], b23 = bp[1], b45 = bp[2], b67 = bp[3];
            unsigned long long av[4] = {a01.x, a01.y, a23.x, a23.y};
            unsigned long long bv[8] = {b01.x, b01.y, b23.x, b23.y, b45.x, b45.y, b67.x, b67.y};
            #pragma unroll
            for (int sp = 0; sp < 4; sp++) {
                #pragma unroll
                for (int c = 0; c < 8; c++) FFMA2(acc[sp][c], av[sp], bv[c]);
            }
        }
        __syncthreads();   // A free for next tile's layer1

        // ---- epilogue: heads partials, width-8 shuffle reduce ----
        float pr[8][4];
        #pragma unroll
        for (int s = 0; s < 8; s++) {
            pr[s][0] = 0.f; pr[s][1] = 0.f; pr[s][2] = 0.f; pr[s][3] = 0.f;
        }
        #pragma unroll
        for (int sp = 0; sp < 4; sp++) {
            #pragma unroll
            for (int c = 0; c < 8; c++) {
                float lo, hi;
                UNPACK2(lo, hi, acc[sp][c]);
                lo = fmaxf(lo, 0.0f);
                hi = fmaxf(hi, 0.0f);
                float4 wo = Wos[c0 + c];
                pr[2 * sp][0]     = fmaf(lo, wo.x, pr[2 * sp][0]);
                pr[2 * sp][1]     = fmaf(lo, wo.y, pr[2 * sp][1]);
                pr[2 * sp][2]     = fmaf(lo, wo.z, pr[2 * sp][2]);
                pr[2 * sp][3]     = fmaf(lo, wo.w, pr[2 * sp][3]);
                pr[2 * sp + 1][0] = fmaf(hi, wo.x, pr[2 * sp + 1][0]);
                pr[2 * sp + 1][1] = fmaf(hi, wo.y, pr[2 * sp + 1][1]);
                pr[2 * sp + 1][2] = fmaf(hi, wo.z, pr[2 * sp + 1][2]);
                pr[2 * sp + 1][3] = fmaf(hi, wo.w, pr[2 * sp + 1][3]);
            }
        }
        #pragma unroll
        for (int s = 0; s < 8; s++) {
            #pragma unroll
            for (int v = 0; v < 4; v++) {
                float val = pr[s][v];
                val += __shfl_down_sync(0xffffffffu, val, 4, 8);
                val += __shfl_down_sync(0xffffffffu, val, 2, 8);
                val += __shfl_down_sync(0xffffffffu, val, 1, 8);
                pr[s][v] = val;
            }
        }
        if (cg == 0) {
            #pragma unroll
            for (int s = 0; s < 8; s++) {
                int id2 = ids_s[s0 + s];
                if (id2 >= 0) {
                    float r0  = pr[s][0] + bias4[0];
                    float r1  = pr[s][1] + bias4[1];
                    float r2  = pr[s][2] + bias4[2];
                    float sig = pr[s][3] + bias4[3];
                    float4 outv;
                    outv.x = 1.0f / (1.0f + __expf(-r0));
                    outv.y = 1.0f / (1.0f + __expf(-r1));
                    outv.z = 1.0f / (1.0f + __expf(-r2));
                    outv.w = sig;
                    g_rgbsig[id2] = outv;
                }
            }
        }
        __syncthreads();   // ids_s reuse
    }
}

// ============================================================
// K3: per-ray composite
// ============================================================
__global__ __launch_bounds__(128) void k3_composite(
    const float* __restrict__ near_, const float* __restrict__ far_,
    float* __restrict__ out)
{
    __shared__ float wtot[4];
    __shared__ float red[12];

    const int n    = blockIdx.x;
    const int tid  = threadIdx.x;
    const int lane = tid & 31;
    const int w    = tid >> 5;

    const float step = __fmul_rn(__fsub_rn(far_[n], near_[n]), 0.0078125f);
    const unsigned bal = g_maskbits[n * 4 + w];
    const bool mask = (bal >> lane) & 1u;

    float4 rs = g_rgbsig[n * NSAMP + tid];
    float alpha = 0.0f;
    if (mask) {
        float tau = fmaxf(rs.w, 0.0f) * step;
        alpha = 1.0f - __expf(-tau);
    }
    float f = 1.0f - alpha + 1e-10f;

    float scan = f;
    #pragma unroll
    for (int off = 1; off < 32; off <<= 1) {
        float v = __shfl_up_sync(0xffffffffu, scan, off);
        if (lane >= off) scan *= v;
    }
    if (lane == 31) wtot[w] = scan;
    __syncthreads();
    float prefix = 1.0f;
    #pragma unroll
    for (int i = 0; i < 4; i++) if (i < w) prefix *= wtot[i];

    float excl = __shfl_up_sync(0xffffffffu, scan, 1);
    if (lane == 0) excl = 1.0f;
    float Tprev = excl * prefix;
    float wgt = alpha * Tprev;

    float c0 = 0.f, c1 = 0.f, c2 = 0.f;
    if (mask) {
        c0 = wgt * rs.x;
        c1 = wgt * rs.y;
        c2 = wgt * rs.z;
    }
    #pragma unroll
    for (int off = 16; off > 0; off >>= 1) {
        c0 += __shfl_down_sync(0xffffffffu, c0, off);
        c1 += __shfl_down_sync(0xffffffffu, c1, off);
        c2 += __shfl_down_sync(0xffffffffu, c2, off);
    }
    if (lane == 0) {
        red[w * 3 + 0] = c0;
        red[w * 3 + 1] = c1;
        red[w * 3 + 2] = c2;
    }
    __syncthreads();
    if (tid == 0) {
        float nohit = wtot[0] * wtot[1] * wtot[2] * wtot[3];
        out[n * 3 + 0] = red[0] + red[3] + red[6] + red[9]  + nohit;
        out[n * 3 + 1] = red[1] + red[4] + red[7] + red[10] + nohit;
        out[n * 3 + 2] = red[2] + red[5] + red[8] + red[11] + nohit;
    }
}

extern "C" void kernel_launch(void* const* d_in, const int* in_sizes, int n_in,
                              void* d_out, int out_size) {
    const float* rays_o  = (const float*)d_in[0];
    const float* rays_d  = (const float*)d_in[1];
    const float* near_   = (const float*)d_in[2];
    const float* far_    = (const float*)d_in[3];
    const float* jitter  = (const float*)d_in[4];
    const float* density = (const float*)d_in[5];
    const float* W1   = (const float*)d_in[6];
    const float* b1   = (const float*)d_in[7];
    const float* W2   = (const float*)d_in[8];
    const float* b2   = (const float*)d_in[9];
    const float* Wsig = (const float*)d_in[10];
    const float* bsig = (const float*)d_in[11];
    const float* Wrgb = (const float*)d_in[12];
    const float* brgb = (const float*)d_in[13];
    float* out = (float*)d_out;

    const int N = in_sizes[2];

    cudaFuncSetAttribute(k2_mlp, cudaFuncAttributeMaxDynamicSharedMemorySize, DYN_SMEM);

    void* cnt_addr = nullptr;
    cudaGetSymbolAddress(&cnt_addr, g_count);
    cudaMemsetAsync(cnt_addr, 0, sizeof(int));

    k1_sample<<<(N + 3) / 4, 512>>>(rays_o, rays_d, near_, far_, jitter, density, N);
    k2_mlp<<<296, 128, DYN_SMEM>>>(W1, b1, W2, b2, Wsig, bsig, Wrgb, brgb);
    k3_composite<<<N, 128>>>(near_, far_, out);
}

// round 12
// speedup vs baseline: 1.6663x; 1.6663x over previous
#include <cuda_runtime.h>
#include <cuda_bf16.h>
#include <cstdint>

#define GRID_N 64
#define NSAMP 128
#define HDIM 64
#define NRAY_MAX 8192
#define NSAMP_TOT (NRAY_MAX * NSAMP)

#define AMINX (-1.25f)
#define AMINY (-1.55f)
#define AMINZ (-1.25f)
#define SCALE (2.5f)

// ---- scratch (device globals) ----
__device__ float4   g_list[NSAMP_TOT];
__device__ float4   g_rgbsig[NSAMP_TOT];
__device__ unsigned g_maskbits[NRAY_MAX * 4];
__device__ int      g_count;

#define FFMA2(acc, a, b) \
    asm("fma.rn.f32x2 %0, %1, %2, %0;" : "+l"(acc) : "l"(a), "l"(b))
#define PACK2(out, lo, hi) \
    asm("mov.b64 %0, {%1, %2};" : "=l"(out) : "f"(lo), "f"(hi))
#define UNPACK2(lo, hi, in) \
    asm("mov.b64 {%0, %1}, %2;" : "=f"(lo), "=f"(hi) : "l"(in))

// ============================================================
// K1: sampling + occupancy mask + global compaction (bit-exact)
// ============================================================
__global__ __launch_bounds__(512) void k1_sample(
    const float* __restrict__ rays_o, const float* __restrict__ rays_d,
    const float* __restrict__ near_, const float* __restrict__ far_,
    const float* __restrict__ jitter, const float* __restrict__ density,
    int N)
{
    __shared__ int warpcnt[16];
    __shared__ int base_s;

    const int tid  = threadIdx.x;
    const int w    = tid >> 5;
    const int lane = tid & 31;
    const int r    = tid >> 7;
    const int s    = tid & 127;
    const int n    = blockIdx.x * 4 + r;
    const bool valid = (n < N);

    bool mask = false;
    float px = 0.f, py = 0.f, pz = 0.f;

    if (valid) {
        const float ox = rays_o[3 * n + 0], oy = rays_o[3 * n + 1], oz = rays_o[3 * n + 2];
        const float dx = rays_d[3 * n + 0], dy = rays_d[3 * n + 1], dz = rays_d[3 * n + 2];
        const float nr = near_[n], fr = far_[n];
        const float step = __fmul_rn(__fsub_rn(fr, nr), 0.0078125f);

        float z = __fadd_rn(nr, __fmul_rn((float)s, step));
        float p0x = __fadd_rn(ox, __fmul_rn(z, dx));
        float p0y = __fadd_rn(oy, __fmul_rn(z, dy));
        float p0z = __fadd_rn(oz, __fmul_rn(z, dz));
        float ux = __fmul_rn(__fdiv_rn(__fsub_rn(p0x, AMINX), SCALE), (float)GRID_N);
        float uy = __fmul_rn(__fdiv_rn(__fsub_rn(p0y, AMINY), SCALE), (float)GRID_N);
        float uz = __fmul_rn(__fdiv_rn(__fsub_rn(p0z, AMINZ), SCALE), (float)GRID_N);
        int ix = (int)floorf(ux);
        int iy = (int)floorf(uy);
        int iz = (int)floorf(uz);
        bool inb = (ix >= 0) & (ix < GRID_N) & (iy >= 0) & (iy < GRID_N)
                 & (iz >= 0) & (iz < GRID_N);
        if (inb) {
            float dv = density[(ix << 12) + (iy << 6) + iz];
            mask = dv > 0.5f;
        }
        float zbase = mask ? z : 0.0f;
        float jit = jitter[n * NSAMP + s];
        float zv = __fadd_rn(zbase, __fmul_rn(jit, step));
        px = __fadd_rn(ox, __fmul_rn(zv, dx));
        py = __fadd_rn(oy, __fmul_rn(zv, dy));
        pz = __fadd_rn(oz, __fmul_rn(zv, dz));
    }

    unsigned bal = __ballot_sync(0xffffffffu, mask);
    int pre = __popc(bal & ((1u << lane) - 1u));
    if (lane == 0) {
        warpcnt[w] = __popc(bal);
        if (valid) g_maskbits[n * 4 + (w & 3)] = bal;
    }
    __syncthreads();
    if (tid == 0) {
        int total = 0;
        #pragma unroll
        for (int i = 0; i < 16; i++) total += warpcnt[i];
        base_s = atomicAdd(&g_count, total);
    }
    int wbase = 0;
    #pragma unroll
    for (int i = 0; i < 16; i++) if (i < w) wbase += warpcnt[i];
    __syncthreads();

    if (mask) {
        int pos = base_s + wbase + pre;
        g_list[pos] = make_float4(px, py, pz, __int_as_float(n * NSAMP + s));
    }
}

// ============================================================
// K2: register-tiled FFMA2 GEMM, 128-sample tiles
//   dyn smem: A[64][128] f32 (k-major layer1 out)  32KB
//             B[64][64]  f32 (plain W2)            16KB   = 48KB
//   thread tile: 4 samples x 16 cols; f32x2 packs COLUMN pairs,
//   so B loads need no duplication (natural adjacent-float pairs).
// ============================================================
#define DYN_SMEM 49152

__global__ __launch_bounds__(128, 4) void k2_mlp(
    const float* __restrict__ W1, const float* __restrict__ b1,
    const float* __restrict__ W2, const float* __restrict__ b2,
    const float* __restrict__ Wsig, const float* __restrict__ bsig,
    const float* __restrict__ Wrgb, const float* __restrict__ brgb)
{
    extern __shared__ __align__(16) char dyn[];
    float* A = (float*)dyn;                       // A[k*128 + s]
    float* B = (float*)(dyn + 32768);             // B[k*64 + c] = W2[k][c]

    __shared__ float  W1s[3 * HDIM];
    __shared__ float  b1s[HDIM];
    __shared__ __align__(8) float b2s[HDIM];
    __shared__ float4 Wos[HDIM];
    __shared__ float  bias4[4];
    __shared__ int    ids_s[128];

    const int tid = threadIdx.x;

    // ---- stage weights ----
    for (int i = tid; i < 3 * HDIM; i += 128) W1s[i] = W1[i];
    if (tid < HDIM) {
        b1s[tid] = b1[tid];
        b2s[tid] = b2[tid];
        Wos[tid] = make_float4(Wrgb[3 * tid + 0], Wrgb[3 * tid + 1],
                               Wrgb[3 * tid + 2], Wsig[tid]);
    }
    if (tid < 3) bias4[tid] = brgb[tid];
    if (tid == 3) bias4[3] = bsig[0];
    #pragma unroll 4
    for (int i = tid; i < HDIM * HDIM; i += 128) B[i] = W2[i];
    __syncthreads();

    const int total  = g_count;
    const int ntiles = (total + 127) >> 7;
    const int s0 = tid & ~3;          // 4-sample group base (32 groups)
    const int c0 = (tid & 3) << 4;    // 16-col group base (4 groups)

    for (int t = blockIdx.x; t < ntiles; t += gridDim.x) {
        // ---- layer 1: one sample per thread, store k-major ----
        const int i = (t << 7) + tid;
        const bool live = (i < total);
        float px = 0.f, py = 0.f, pz = 0.f;
        int id = -1;
        if (live) {
            float4 e = g_list[i];
            px = e.x; py = e.y; pz = e.z;
            id = __float_as_int(e.w);
        }
        ids_s[tid] = id;
        #pragma unroll
        for (int k = 0; k < HDIM; k++) {
            float a = fmaf(px, W1s[k], fmaf(py, W1s[HDIM + k], fmaf(pz, W1s[2 * HDIM + k], b1s[k])));
            A[k * 128 + tid] = fmaxf(a, 0.0f);
        }
        __syncthreads();

        // ---- GEMM: acc[sp][cp], f32x2 over column pairs ----
        unsigned long long acc[4][8];
        {
            const unsigned long long* b2p = reinterpret_cast<const unsigned long long*>(&b2s[c0]);
            #pragma unroll
            for (int cp = 0; cp < 8; cp++) {
                unsigned long long p = b2p[cp];
                acc[0][cp] = p; acc[1][cp] = p; acc[2][cp] = p; acc[3][cp] = p;
            }
        }
        #pragma unroll 4
        for (int k = 0; k < HDIM; k++) {
            float4 a4 = *reinterpret_cast<const float4*>(&A[k * 128 + s0]);
            unsigned long long av[4];
            PACK2(av[0], a4.x, a4.x);
            PACK2(av[1], a4.y, a4.y);
            PACK2(av[2], a4.z, a4.z);
            PACK2(av[3], a4.w, a4.w);
            const ulonglong2* bp = reinterpret_cast<const ulonglong2*>(&B[k * 64 + c0]);
            ulonglong2 q0 = bp[0], q1 = bp[1], q2 = bp[2], q3 = bp[3];
            unsigned long long bv[8] = {q0.x, q0.y, q1.x, q1.y, q2.x, q2.y, q3.x, q3.y};
            #pragma unroll
            for (int sp = 0; sp < 4; sp++) {
                #pragma unroll
                for (int cp = 0; cp < 8; cp++) FFMA2(acc[sp][cp], av[sp], bv[cp]);
            }
        }
        __syncthreads();   // A free for next tile

        // ---- epilogue: relu + heads, width-4 shuffle reduce over col groups ----
        #pragma unroll
        for (int sp = 0; sp < 4; sp++) {
            float pr0 = 0.f, pr1 = 0.f, pr2 = 0.f, pr3 = 0.f;
            #pragma unroll
            for (int cp = 0; cp < 8; cp++) {
                float lo, hi;
                UNPACK2(lo, hi, acc[sp][cp]);
                lo = fmaxf(lo, 0.0f);
                hi = fmaxf(hi, 0.0f);
                float4 wl = Wos[c0 + 2 * cp];
                float4 wh = Wos[c0 + 2 * cp + 1];
                pr0 = fmaf(lo, wl.x, pr0); pr0 = fmaf(hi, wh.x, pr0);
                pr1 = fmaf(lo, wl.y, pr1); pr1 = fmaf(hi, wh.y, pr1);
                pr2 = fmaf(lo, wl.z, pr2); pr2 = fmaf(hi, wh.z, pr2);
                pr3 = fmaf(lo, wl.w, pr3); pr3 = fmaf(hi, wh.w, pr3);
            }
            pr0 += __shfl_down_sync(0xffffffffu, pr0, 2, 4);
            pr1 += __shfl_down_sync(0xffffffffu, pr1, 2, 4);
            pr2 += __shfl_down_sync(0xffffffffu, pr2, 2, 4);
            pr3 += __shfl_down_sync(0xffffffffu, pr3, 2, 4);
            pr0 += __shfl_down_sync(0xffffffffu, pr0, 1, 4);
            pr1 += __shfl_down_sync(0xffffffffu, pr1, 1, 4);
            pr2 += __shfl_down_sync(0xffffffffu, pr2, 1, 4);
            pr3 += __shfl_down_sync(0xffffffffu, pr3, 1, 4);
            if ((tid & 3) == 0) {
                int id2 = ids_s[s0 + sp];
                if (id2 >= 0) {
                    float4 outv;
                    outv.x = 1.0f / (1.0f + __expf(-(pr0 + bias4[0])));
                    outv.y = 1.0f / (1.0f + __expf(-(pr1 + bias4[1])));
                    outv.z = 1.0f / (1.0f + __expf(-(pr2 + bias4[2])));
                    outv.w = pr3 + bias4[3];
                    g_rgbsig[id2] = outv;
                }
            }
        }
        __syncthreads();   // ids_s reuse
    }
}

// ============================================================
// K3: per-ray composite
// ============================================================
__global__ __launch_bounds__(128) void k3_composite(
    const float* __restrict__ near_, const float* __restrict__ far_,
    float* __restrict__ out)
{
    __shared__ float wtot[4];
    __shared__ float red[12];

    const int n    = blockIdx.x;
    const int tid  = threadIdx.x;
    const int lane = tid & 31;
    const int w    = tid >> 5;

    const float step = __fmul_rn(__fsub_rn(far_[n], near_[n]), 0.0078125f);
    const unsigned bal = g_maskbits[n * 4 + w];
    const bool mask = (bal >> lane) & 1u;

    float4 rs = g_rgbsig[n * NSAMP + tid];
    float alpha = 0.0f;
    if (mask) {
        float tau = fmaxf(rs.w, 0.0f) * step;
        alpha = 1.0f - __expf(-tau);
    }
    float f = 1.0f - alpha + 1e-10f;

    float scan = f;
    #pragma unroll
    for (int off = 1; off < 32; off <<= 1) {
        float v = __shfl_up_sync(0xffffffffu, scan, off);
        if (lane >= off) scan *= v;
    }
    if (lane == 31) wtot[w] = scan;
    __syncthreads();
    float prefix = 1.0f;
    #pragma unroll
    for (int i = 0; i < 4; i++) if (i < w) prefix *= wtot[i];

    float excl = __shfl_up_sync(0xffffffffu, scan, 1);
    if (lane == 0) excl = 1.0f;
    float Tprev = excl * prefix;
    float wgt = alpha * Tprev;

    float c0 = 0.f, c1 = 0.f, c2 = 0.f;
    if (mask) {
        c0 = wgt * rs.x;
        c1 = wgt * rs.y;
        c2 = wgt * rs.z;
    }
    #pragma unroll
    for (int off = 16; off > 0; off >>= 1) {
        c0 += __shfl_down_sync(0xffffffffu, c0, off);
        c1 += __shfl_down_sync(0xffffffffu, c1, off);
        c2 += __shfl_down_sync(0xffffffffu, c2, off);
    }
    if (lane == 0) {
        red[w * 3 + 0] = c0;
        red[w * 3 + 1] = c1;
        red[w * 3 + 2] = c2;
    }
    __syncthreads();
    if (tid == 0) {
        float nohit = wtot[0] * wtot[1] * wtot[2] * wtot[3];
        out[n * 3 + 0] = red[0] + red[3] + red[6] + red[9]  + nohit;
        out[n * 3 + 1] = red[1] + red[4] + red[7] + red[10] + nohit;
        out[n * 3 + 2] = red[2] + red[5] + red[8] + red[11] + nohit;
    }
}

extern "C" void kernel_launch(void* const* d_in, const int* in_sizes, int n_in,
                              void* d_out, int out_size) {
    const float* rays_o  = (const float*)d_in[0];
    const float* rays_d  = (const float*)d_in[1];
    const float* near_   = (const float*)d_in[2];
    const float* far_    = (const float*)d_in[3];
    const float* jitter  = (const float*)d_in[4];
    const float* density = (const float*)d_in[5];
    const float* W1   = (const float*)d_in[6];
    const float* b1   = (const float*)d_in[7];
    const float* W2   = (const float*)d_in[8];
    const float* b2   = (const float*)d_in[9];
    const float* Wsig = (const float*)d_in[10];
    const float* bsig = (const float*)d_in[11];
    const float* Wrgb = (const float*)d_in[12];
    const float* brgb = (const float*)d_in[13];
    float* out = (float*)d_out;

    const int N = in_sizes[2];

    cudaFuncSetAttribute(k2_mlp, cudaFuncAttributeMaxDynamicSharedMemorySize, DYN_SMEM);

    void* cnt_addr = nullptr;
    cudaGetSymbolAddress(&cnt_addr, g_count);
    cudaMemsetAsync(cnt_addr, 0, sizeof(int));

    k1_sample<<<(N + 3) / 4, 512>>>(rays_o, rays_d, near_, far_, jitter, density, N);
    k2_mlp<<<592, 128, DYN_SMEM>>>(W1, b1, W2, b2, Wsig, bsig, Wrgb, brgb);
    k3_composite<<<N, 128>>>(near_, far_, out);
}

// round 14
// speedup vs baseline: 3.5277x; 2.1171x over previous
#include <cuda_runtime.h>
#include <cuda_bf16.h>
#include <cstdint>

#define GRID_N 64
#define NSAMP 128
#define HDIM 64
#define NRAY_MAX 8192
#define NSAMP_TOT (NRAY_MAX * NSAMP)

#define AMINX (-1.25f)
#define AMINY (-1.55f)
#define AMINZ (-1.25f)
#define SCALE (2.5f)

// ---- scratch (device globals) ----
__device__ float4   g_list[NSAMP_TOT];
__device__ float4   g_rgbsig[NSAMP_TOT];
__device__ unsigned g_maskbits[NRAY_MAX * 4];
__device__ int      g_count;

#define BF16X2(r, hi, lo) \
    asm("cvt.rn.bf16x2.f32 %0, %1, %2;" : "=r"(r) : "f"(hi), "f"(lo))

__device__ __forceinline__ void mma16816(float* d, const uint32_t* a,
                                         uint32_t b0, uint32_t b1) {
    asm volatile(
        "mma.sync.aligned.m16n8k16.row.col.f32.bf16.bf16.f32 "
        "{%0,%1,%2,%3}, {%4,%5,%6,%7}, {%8,%9}, {%0,%1,%2,%3};"
        : "+f"(d[0]), "+f"(d[1]), "+f"(d[2]), "+f"(d[3])
        : "r"(a[0]), "r"(a[1]), "r"(a[2]), "r"(a[3]), "r"(b0), "r"(b1));
}

// ============================================================
// K1: sampling + occupancy mask + global compaction (bit-exact)
// ============================================================
__global__ __launch_bounds__(512) void k1_sample(
    const float* __restrict__ rays_o, const float* __restrict__ rays_d,
    const float* __restrict__ near_, const float* __restrict__ far_,
    const float* __restrict__ jitter, const float* __restrict__ density,
    int N)
{
    __shared__ int warpcnt[16];
    __shared__ int base_s;

    const int tid  = threadIdx.x;
    const int w    = tid >> 5;
    const int lane = tid & 31;
    const int r    = tid >> 7;
    const int s    = tid & 127;
    const int n    = blockIdx.x * 4 + r;
    const bool valid = (n < N);

    bool mask = false;
    float px = 0.f, py = 0.f, pz = 0.f;

    if (valid) {
        const float ox = rays_o[3 * n + 0], oy = rays_o[3 * n + 1], oz = rays_o[3 * n + 2];
        const float dx = rays_d[3 * n + 0], dy = rays_d[3 * n + 1], dz = rays_d[3 * n + 2];
        const float nr = near_[n], fr = far_[n];
        const float step = __fmul_rn(__fsub_rn(fr, nr), 0.0078125f);

        float z = __fadd_rn(nr, __fmul_rn((float)s, step));
        float p0x = __fadd_rn(ox, __fmul_rn(z, dx));
        float p0y = __fadd_rn(oy, __fmul_rn(z, dy));
        float p0z = __fadd_rn(oz, __fmul_rn(z, dz));
        float ux = __fmul_rn(__fdiv_rn(__fsub_rn(p0x, AMINX), SCALE), (float)GRID_N);
        float uy = __fmul_rn(__fdiv_rn(__fsub_rn(p0y, AMINY), SCALE), (float)GRID_N);
        float uz = __fmul_rn(__fdiv_rn(__fsub_rn(p0z, AMINZ), SCALE), (float)GRID_N);
        int ix = (int)floorf(ux);
        int iy = (int)floorf(uy);
        int iz = (int)floorf(uz);
        bool inb = (ix >= 0) & (ix < GRID_N) & (iy >= 0) & (iy < GRID_N)
                 & (iz >= 0) & (iz < GRID_N);
        if (inb) {
            float dv = density[(ix << 12) + (iy << 6) + iz];
            mask = dv > 0.5f;
        }
        float zbase = mask ? z : 0.0f;
        float jit = jitter[n * NSAMP + s];
        float zv = __fadd_rn(zbase, __fmul_rn(jit, step));
        px = __fadd_rn(ox, __fmul_rn(zv, dx));
        py = __fadd_rn(oy, __fmul_rn(zv, dy));
        pz = __fadd_rn(oz, __fmul_rn(zv, dz));
    }

    unsigned bal = __ballot_sync(0xffffffffu, mask);
    int pre = __popc(bal & ((1u << lane) - 1u));
    if (lane == 0) {
        warpcnt[w] = __popc(bal);
        if (valid) g_maskbits[n * 4 + (w & 3)] = bal;
    }
    __syncthreads();
    if (tid == 0) {
        int total = 0;
        #pragma unroll
        for (int i = 0; i < 16; i++) total += warpcnt[i];
        base_s = atomicAdd(&g_count, total);
    }
    int wbase = 0;
    #pragma unroll
    for (int i = 0; i < 16; i++) if (i < w) wbase += warpcnt[i];
    __syncthreads();

    if (mask) {
        int pos = base_s + wbase + pre;
        g_list[pos] = make_float4(px, py, pz, __int_as_float(n * NSAMP + s));
    }
}

// ============================================================
// K2: layer-2 GEMM via mma.sync m16n8k16 bf16 (hi/lo split, f32 acc)
//   CTA = 256 threads (8 warps), tile = 256 samples.
//   Each warp: 32 rows x 64 cols = 2(m) x 8(n) tiles x 4 k-chunks,
//   3 passes (hi*hi + lo*hi + hi*lo) = 192 HMMA per warp-tile.
//   dyn smem: Ahi[256][72bf16] rows 144B (conflict-free frag loads)
//             Alo same; Bhi/Blo = W2^T [64][68bf16] rows 136B
// ============================================================
#define A_STRIDE 144
#define B_STRIDE 136
#define OFF_AHI 0
#define OFF_ALO (256 * A_STRIDE)
#define OFF_BHI (2 * 256 * A_STRIDE)
#define OFF_BLO (2 * 256 * A_STRIDE + 64 * B_STRIDE)
#define DYN_SMEM (2 * 256 * A_STRIDE + 2 * 64 * B_STRIDE)   // 91136

__global__ __launch_bounds__(256, 2) void k2_mlp(
    const float* __restrict__ W1, const float* __restrict__ b1,
    const float* __restrict__ W2, const float* __restrict__ b2,
    const float* __restrict__ Wsig, const float* __restrict__ bsig,
    const float* __restrict__ Wrgb, const float* __restrict__ brgb)
{
    extern __shared__ __align__(16) char dyn[];
    char* const Ahi = dyn + OFF_AHI;
    char* const Alo = dyn + OFF_ALO;
    char* const Bhi = dyn + OFF_BHI;
    char* const Blo = dyn + OFF_BLO;

    __shared__ float  W1s[3 * HDIM];
    __shared__ float  b1s[HDIM];
    __shared__ __align__(8) float b2s[HDIM];
    __shared__ float4 Wos[HDIM];
    __shared__ float  bias4[4];
    __shared__ int    ids_s[256];

    const int tid  = threadIdx.x;
    const int w    = tid >> 5;
    const int lane = tid & 31;
    const int g    = lane >> 2;     // group id 0..7
    const int tg   = lane & 3;      // thread in group

    // ---- stage small weights ----
    for (int i = tid; i < 3 * HDIM; i += 256) W1s[i] = W1[i];
    if (tid < HDIM) {
        b1s[tid] = b1[tid];
        b2s[tid] = b2[tid];
        Wos[tid] = make_float4(Wrgb[3 * tid + 0], Wrgb[3 * tid + 1],
                               Wrgb[3 * tid + 2], Wsig[tid]);
    }
    if (tid < 3) bias4[tid] = brgb[tid];
    if (tid == 3) bias4[3] = bsig[0];

    // ---- B tiles: Bsm[n][k] = W2[k][n], bf16 hi + exact-residual lo ----
    for (int idx = tid; idx < 64 * 32; idx += 256) {
        int nn = idx >> 5, kp = idx & 31;           // k pair
        float w0 = W2[(2 * kp) * 64 + nn];
        float w1 = W2[(2 * kp + 1) * 64 + nn];
        uint32_t hp; BF16X2(hp, w1, w0);
        float hf0 = __uint_as_float(hp << 16);
        float hf1 = __uint_as_float(hp & 0xffff0000u);
        uint32_t lp; BF16X2(lp, w1 - hf1, w0 - hf0);
        *(uint32_t*)(Bhi + nn * B_STRIDE + kp * 4) = hp;
        *(uint32_t*)(Blo + nn * B_STRIDE + kp * 4) = lp;
    }
    __syncthreads();

    // per-thread constant b2 pairs for accumulator init
    float2 bb[8];
    #pragma unroll
    for (int j = 0; j < 8; j++)
        bb[j] = *(const float2*)&b2s[8 * j + 2 * tg];

    const int total  = g_count;
    const int ntiles = (total + 255) >> 8;

    for (int t = blockIdx.x; t < ntiles; t += gridDim.x) {
        // ---- layer 1: one sample per thread -> split bf16 hi/lo into A ----
        const int i = (t << 8) + tid;
        const bool live = (i < total);
        float px = 0.f, py = 0.f, pz = 0.f;
        int id = -1;
        if (live) {
            float4 e = g_list[i];
            px = e.x; py = e.y; pz = e.z;
            id = __float_as_int(e.w);
        }
        ids_s[tid] = id;
        {
            const uint32_t ro = (uint32_t)tid * A_STRIDE;
            #pragma unroll
            for (int k = 0; k < HDIM; k += 2) {
                float a0 = fmaf(px, W1s[k],     fmaf(py, W1s[HDIM + k],     fmaf(pz, W1s[2 * HDIM + k],     b1s[k])));
                float a1 = fmaf(px, W1s[k + 1], fmaf(py, W1s[HDIM + k + 1], fmaf(pz, W1s[2 * HDIM + k + 1], b1s[k + 1])));
                a0 = fmaxf(a0, 0.0f);
                a1 = fmaxf(a1, 0.0f);
                uint32_t hp; BF16X2(hp, a1, a0);
                float hf0 = __uint_as_float(hp << 16);
                float hf1 = __uint_as_float(hp & 0xffff0000u);
                uint32_t lp; BF16X2(lp, a1 - hf1, a0 - hf0);
                *(uint32_t*)(Ahi + ro + k * 2) = hp;
                *(uint32_t*)(Alo + ro + k * 2) = lp;
            }
        }
        __syncthreads();

        // ---- MMA: 2 m-tiles x 8 n-tiles x 4 k-chunks x 3 passes ----
        float d[2][8][4];
        #pragma unroll
        for (int mt = 0; mt < 2; mt++)
            #pragma unroll
            for (int j = 0; j < 8; j++) {
                d[mt][j][0] = bb[j].x; d[mt][j][1] = bb[j].y;
                d[mt][j][2] = bb[j].x; d[mt][j][3] = bb[j].y;
            }

        #pragma unroll
        for (int kc = 0; kc < 4; kc++) {
            const int kb = kc * 16;
            uint32_t ah[2][4], al[2][4];
            #pragma unroll
            for (int mt = 0; mt < 2; mt++) {
                const int rb = w * 32 + mt * 16 + g;
                const char* ph = Ahi + rb * A_STRIDE + (kb + 2 * tg) * 2;
                const char* pl = Alo + rb * A_STRIDE + (kb + 2 * tg) * 2;
                ah[mt][0] = *(const uint32_t*)(ph);
                ah[mt][1] = *(const uint32_t*)(ph + 8 * A_STRIDE);
                ah[mt][2] = *(const uint32_t*)(ph + 16);
                ah[mt][3] = *(const uint32_t*)(ph + 8 * A_STRIDE + 16);
                al[mt][0] = *(const uint32_t*)(pl);
                al[mt][1] = *(const uint32_t*)(pl + 8 * A_STRIDE);
                al[mt][2] = *(const uint32_t*)(pl + 16);
                al[mt][3] = *(const uint32_t*)(pl + 8 * A_STRIDE + 16);
            }
            #pragma unroll
            for (int j = 0; j < 8; j++) {
                const char* pb = Bhi + (8 * j + g) * B_STRIDE + (kb + 2 * tg) * 2;
                const char* ql = Blo + (8 * j + g) * B_STRIDE + (kb + 2 * tg) * 2;
                uint32_t bh0 = *(const uint32_t*)(pb);
                uint32_t bh1 = *(const uint32_t*)(pb + 16);
                uint32_t bl0 = *(const uint32_t*)(ql);
                uint32_t bl1 = *(const uint32_t*)(ql + 16);
                mma16816(d[0][j], ah[0], bh0, bh1);
                mma16816(d[1][j], ah[1], bh0, bh1);
                mma16816(d[0][j], al[0], bh0, bh1);
                mma16816(d[1][j], al[1], bh0, bh1);
                mma16816(d[0][j], ah[0], bl0, bl1);
                mma16816(d[1][j], ah[1], bl0, bl1);
            }
        }

        // ---- epilogue: relu + head dot products, reduce over tg (width 4) ----
        float pr[4][4];
        #pragma unroll
        for (int q = 0; q < 4; q++) {
            pr[q][0] = 0.f; pr[q][1] = 0.f; pr[q][2] = 0.f; pr[q][3] = 0.f;
        }
        #pragma unroll
        for (int mt = 0; mt < 2; mt++) {
            #pragma unroll
            for (int j = 0; j < 8; j++) {
                float4 wl = Wos[8 * j + 2 * tg];
                float4 wh = Wos[8 * j + 2 * tg + 1];
                float h0 = fmaxf(d[mt][j][0], 0.f);
                float h1 = fmaxf(d[mt][j][1], 0.f);
                float h2 = fmaxf(d[mt][j][2], 0.f);
                float h3 = fmaxf(d[mt][j][3], 0.f);
                pr[2 * mt][0] = fmaf(h0, wl.x, fmaf(h1, wh.x, pr[2 * mt][0]));
                pr[2 * mt][1] = fmaf(h0, wl.y, fmaf(h1, wh.y, pr[2 * mt][1]));
                pr[2 * mt][2] = fmaf(h0, wl.z, fmaf(h1, wh.z, pr[2 * mt][2]));
                pr[2 * mt][3] = fmaf(h0, wl.w, fmaf(h1, wh.w, pr[2 * mt][3]));
                pr[2 * mt + 1][0] = fmaf(h2, wl.x, fmaf(h3, wh.x, pr[2 * mt + 1][0]));
                pr[2 * mt + 1][1] = fmaf(h2, wl.y, fmaf(h3, wh.y, pr[2 * mt + 1][1]));
                pr[2 * mt + 1][2] = fmaf(h2, wl.z, fmaf(h3, wh.z, pr[2 * mt + 1][2]));
                pr[2 * mt + 1][3] = fmaf(h2, wl.w, fmaf(h3, wh.w, pr[2 * mt + 1][3]));
            }
        }
        #pragma unroll
        for (int q = 0; q < 4; q++) {
            #pragma unroll
            for (int v = 0; v < 4; v++) {
                float val = pr[q][v];
                val += __shfl_down_sync(0xffffffffu, val, 2, 4);
                val += __shfl_down_sync(0xffffffffu, val, 1, 4);
                pr[q][v] = val;
            }
        }
        if (tg == 0) {
            const int rows[4] = { w * 32 + g, w * 32 + g + 8,
                                  w * 32 + 16 + g, w * 32 + 24 + g };
            #pragma unroll
            for (int q = 0; q < 4; q++) {
                int id2 = ids_s[rows[q]];
                if (id2 >= 0) {
                    float4 outv;
                    outv.x = 1.0f / (1.0f + __expf(-(pr[q][0] + bias4[0])));
                    outv.y = 1.0f / (1.0f + __expf(-(pr[q][1] + bias4[1])));
                    outv.z = 1.0f / (1.0f + __expf(-(pr[q][2] + bias4[2])));
                    outv.w = pr[q][3] + bias4[3];
                    g_rgbsig[id2] = outv;
                }
            }
        }
        __syncthreads();   // A / ids_s reuse next tile
    }
}

// ============================================================
// K3: per-ray composite
// ============================================================
__global__ __launch_bounds__(128) void k3_composite(
    const float* __restrict__ near_, const float* __restrict__ far_,
    float* __restrict__ out)
{
    __shared__ float wtot[4];
    __shared__ float red[12];

    const int n    = blockIdx.x;
    const int tid  = threadIdx.x;
    const int lane = tid & 31;
    const int w    = tid >> 5;

    const float step = __fmul_rn(__fsub_rn(far_[n], near_[n]), 0.0078125f);
    const unsigned bal = g_maskbits[n * 4 + w];
    const bool mask = (bal >> lane) & 1u;

    float4 rs = g_rgbsig[n * NSAMP + tid];
    float alpha = 0.0f;
    if (mask) {
        float tau = fmaxf(rs.w, 0.0f) * step;
        alpha = 1.0f - __expf(-tau);
    }
    float f = 1.0f - alpha + 1e-10f;

    float scan = f;
    #pragma unroll
    for (int off = 1; off < 32; off <<= 1) {
        float v = __shfl_up_sync(0xffffffffu, scan, off);
        if (lane >= off) scan *= v;
    }
    if (lane == 31) wtot[w] = scan;
    __syncthreads();
    float prefix = 1.0f;
    #pragma unroll
    for (int i = 0; i < 4; i++) if (i < w) prefix *= wtot[i];

    float excl = __shfl_up_sync(0xffffffffu, scan, 1);
    if (lane == 0) excl = 1.0f;
    float Tprev = excl * prefix;
    float wgt = alpha * Tprev;

    float c0 = 0.f, c1 = 0.f, c2 = 0.f;
    if (mask) {
        c0 = wgt * rs.x;
        c1 = wgt * rs.y;
        c2 = wgt * rs.z;
    }
    #pragma unroll
    for (int off = 16; off > 0; off >>= 1) {
        c0 += __shfl_down_sync(0xffffffffu, c0, off);
        c1 += __shfl_down_sync(0xffffffffu, c1, off);
        c2 += __shfl_down_sync(0xffffffffu, c2, off);
    }
    if (lane == 0) {
        red[w * 3 + 0] = c0;
        red[w * 3 + 1] = c1;
        red[w * 3 + 2] = c2;
    }
    __syncthreads();
    if (tid == 0) {
        float nohit = wtot[0] * wtot[1] * wtot[2] * wtot[3];
        out[n * 3 + 0] = red[0] + red[3] + red[6] + red[9]  + nohit;
        out[n * 3 + 1] = red[1] + red[4] + red[7] + red[10] + nohit;
        out[n * 3 + 2] = red[2] + red[5] + red[8] + red[11] + nohit;
    }
}

extern "C" void kernel_launch(void* const* d_in, const int* in_sizes, int n_in,
                              void* d_out, int out_size) {
    const float* rays_o  = (const float*)d_in[0];
    const float* rays_d  = (const float*)d_in[1];
    const float* near_   = (const float*)d_in[2];
    const float* far_    = (const float*)d_in[3];
    const float* jitter  = (const float*)d_in[4];
    const float* density = (const float*)d_in[5];
    const float* W1   = (const float*)d_in[6];
    const float* b1   = (const float*)d_in[7];
    const float* W2   = (const float*)d_in[8];
    const float* b2   = (const float*)d_in[9];
    const float* Wsig = (const float*)d_in[10];
    const float* bsig = (const float*)d_in[11];
    const float* Wrgb = (const float*)d_in[12];
    const float* brgb = (const float*)d_in[13];
    float* out = (float*)d_out;

    const int N = in_sizes[2];

    cudaFuncSetAttribute(k2_mlp, cudaFuncAttributeMaxDynamicSharedMemorySize, DYN_SMEM);

    void* cnt_addr = nullptr;
    cudaGetSymbolAddress(&cnt_addr, g_count);
    cudaMemsetAsync(cnt_addr, 0, sizeof(int));

    k1_sample<<<(N + 3) / 4, 512>>>(rays_o, rays_d, near_, far_, jitter, density, N);
    k2_mlp<<<296, 256, DYN_SMEM>>>(W1, b1, W2, b2, Wsig, bsig, Wrgb, brgb);
    k3_composite<<<N, 128>>>(near_, far_, out);
}

// round 15
// speedup vs baseline: 3.5650x; 1.0106x over previous
#include <cuda_runtime.h>
#include <cuda_bf16.h>
#include <cstdint>

#define GRID_N 64
#define NSAMP 128
#define HDIM 64
#define NRAY_MAX 8192
#define NSAMP_TOT (NRAY_MAX * NSAMP)

#define AMINX (-1.25f)
#define AMINY (-1.55f)
#define AMINZ (-1.25f)
#define SCALE (2.5f)

// ---- scratch (device globals) ----
__device__ float4   g_list[NSAMP_TOT];
__device__ float4   g_rgbsig[NSAMP_TOT];
__device__ unsigned g_maskbits[NRAY_MAX * 4];
__device__ int      g_count;

#define BF16X2(r, hi, lo) \
    asm("cvt.rn.bf16x2.f32 %0, %1, %2;" : "=r"(r) : "f"(hi), "f"(lo))

__device__ __forceinline__ void mma16816(float* d, const uint32_t* a,
                                         uint32_t b0, uint32_t b1) {
    asm volatile(
        "mma.sync.aligned.m16n8k16.row.col.f32.bf16.bf16.f32 "
        "{%0,%1,%2,%3}, {%4,%5,%6,%7}, {%8,%9}, {%0,%1,%2,%3};"
        : "+f"(d[0]), "+f"(d[1]), "+f"(d[2]), "+f"(d[3])
        : "r"(a[0]), "r"(a[1]), "r"(a[2]), "r"(a[3]), "r"(b0), "r"(b1));
}

// ============================================================
// K1: sampling + occupancy mask + global compaction (bit-exact)
//     restructured: density load issued early, short post-load tail
// ============================================================
__global__ __launch_bounds__(512) void k1_sample(
    const float* __restrict__ rays_o, const float* __restrict__ rays_d,
    const float* __restrict__ near_, const float* __restrict__ far_,
    const float* __restrict__ jitter, const float* __restrict__ density,
    int N)
{
    __shared__ int warpcnt[16];
    __shared__ int base_s;

    const int tid  = threadIdx.x;
    const int w    = tid >> 5;
    const int lane = tid & 31;
    const int r    = tid >> 7;
    const int s    = tid & 127;
    const int n    = blockIdx.x * 4 + r;
    const bool valid = (n < N);

    bool mask = false;
    float px = 0.f, py = 0.f, pz = 0.f;

    if (valid) {
        // issue the (DRAM-cold) jitter load first
        const float jit = __ldg(&jitter[n * NSAMP + s]);
        const float ox = rays_o[3 * n + 0], oy = rays_o[3 * n + 1], oz = rays_o[3 * n + 2];
        const float dx = rays_d[3 * n + 0], dy = rays_d[3 * n + 1], dz = rays_d[3 * n + 2];
        const float nr = near_[n], fr = far_[n];
        const float step = __fmul_rn(__fsub_rn(fr, nr), 0.0078125f);

        // ---- density-address chain (exact-rounded, matches JAX) ----
        const float z = __fadd_rn(nr, __fmul_rn((float)s, step));
        const float p0x = __fadd_rn(ox, __fmul_rn(z, dx));
        const float p0y = __fadd_rn(oy, __fmul_rn(z, dy));
        const float p0z = __fadd_rn(oz, __fmul_rn(z, dz));
        const float ux = __fmul_rn(__fdiv_rn(__fsub_rn(p0x, AMINX), SCALE), (float)GRID_N);
        const float uy = __fmul_rn(__fdiv_rn(__fsub_rn(p0y, AMINY), SCALE), (float)GRID_N);
        const float uz = __fmul_rn(__fdiv_rn(__fsub_rn(p0z, AMINZ), SCALE), (float)GRID_N);
        const int ix = (int)floorf(ux);
        const int iy = (int)floorf(uy);
        const int iz = (int)floorf(uz);
        const bool inb = (ix >= 0) & (ix < GRID_N) & (iy >= 0) & (iy < GRID_N)
                       & (iz >= 0) & (iz < GRID_N);
        // issue density load NOW (clamped addr; result gated by inb)
        const int cx = min(max(ix, 0), GRID_N - 1);
        const int cy = min(max(iy, 0), GRID_N - 1);
        const int cz = min(max(iz, 0), GRID_N - 1);
        const float dv = __ldg(&density[(cx << 12) + (cy << 6) + cz]);

        // overlap: both zv candidates while dv is in flight
        const float js  = __fmul_rn(jit, step);
        const float zvA = __fadd_rn(z, js);   // mask true  (zbase = z)
        const float zvB = js;                 // mask false (zbase = 0; 0+js == js exactly)

        mask = inb && (dv > 0.5f);
        const float zv = mask ? zvA : zvB;
        px = __fadd_rn(ox, __fmul_rn(zv, dx));
        py = __fadd_rn(oy, __fmul_rn(zv, dy));
        pz = __fadd_rn(oz, __fmul_rn(zv, dz));
    }

    unsigned bal = __ballot_sync(0xffffffffu, mask);
    int pre = __popc(bal & ((1u << lane) - 1u));
    if (lane == 0) {
        warpcnt[w] = __popc(bal);
        if (valid) g_maskbits[n * 4 + (w & 3)] = bal;
    }
    __syncthreads();
    if (tid == 0) {
        int total = 0;
        #pragma unroll
        for (int i = 0; i < 16; i++) total += warpcnt[i];
        base_s = atomicAdd(&g_count, total);
    }
    int wbase = 0;
    #pragma unroll
    for (int i = 0; i < 16; i++) if (i < w) wbase += warpcnt[i];
    __syncthreads();

    if (mask) {
        int pos = base_s + wbase + pre;
        g_list[pos] = make_float4(px, py, pz, __int_as_float(n * NSAMP + s));
    }
}

// ============================================================
// K2: layer-2 GEMM via mma.sync m16n8k16 bf16 (hi/lo split, f32 acc)
//     (unchanged from round 14 — protect the win)
// ============================================================
#define A_STRIDE 144
#define B_STRIDE 136
#define OFF_AHI 0
#define OFF_ALO (256 * A_STRIDE)
#define OFF_BHI (2 * 256 * A_STRIDE)
#define OFF_BLO (2 * 256 * A_STRIDE + 64 * B_STRIDE)
#define DYN_SMEM (2 * 256 * A_STRIDE + 2 * 64 * B_STRIDE)   // 91136

__global__ __launch_bounds__(256, 2) void k2_mlp(
    const float* __restrict__ W1, const float* __restrict__ b1,
    const float* __restrict__ W2, const float* __restrict__ b2,
    const float* __restrict__ Wsig, const float* __restrict__ bsig,
    const float* __restrict__ Wrgb, const float* __restrict__ brgb)
{
    extern __shared__ __align__(16) char dyn[];
    char* const Ahi = dyn + OFF_AHI;
    char* const Alo = dyn + OFF_ALO;
    char* const Bhi = dyn + OFF_BHI;
    char* const Blo = dyn + OFF_BLO;

    __shared__ float  W1s[3 * HDIM];
    __shared__ float  b1s[HDIM];
    __shared__ __align__(8) float b2s[HDIM];
    __shared__ float4 Wos[HDIM];
    __shared__ float  bias4[4];
    __shared__ int    ids_s[256];

    const int tid  = threadIdx.x;
    const int w    = tid >> 5;
    const int lane = tid & 31;
    const int g    = lane >> 2;
    const int tg   = lane & 3;

    for (int i = tid; i < 3 * HDIM; i += 256) W1s[i] = W1[i];
    if (tid < HDIM) {
        b1s[tid] = b1[tid];
        b2s[tid] = b2[tid];
        Wos[tid] = make_float4(Wrgb[3 * tid + 0], Wrgb[3 * tid + 1],
                               Wrgb[3 * tid + 2], Wsig[tid]);
    }
    if (tid < 3) bias4[tid] = brgb[tid];
    if (tid == 3) bias4[3] = bsig[0];

    for (int idx = tid; idx < 64 * 32; idx += 256) {
        int nn = idx >> 5, kp = idx & 31;
        float w0 = W2[(2 * kp) * 64 + nn];
        float w1 = W2[(2 * kp + 1) * 64 + nn];
        uint32_t hp; BF16X2(hp, w1, w0);
        float hf0 = __uint_as_float(hp << 16);
        float hf1 = __uint_as_float(hp & 0xffff0000u);
        uint32_t lp; BF16X2(lp, w1 - hf1, w0 - hf0);
        *(uint32_t*)(Bhi + nn * B_STRIDE + kp * 4) = hp;
        *(uint32_t*)(Blo + nn * B_STRIDE + kp * 4) = lp;
    }
    __syncthreads();

    float2 bb[8];
    #pragma unroll
    for (int j = 0; j < 8; j++)
        bb[j] = *(const float2*)&b2s[8 * j + 2 * tg];

    const int total  = g_count;
    const int ntiles = (total + 255) >> 8;

    for (int t = blockIdx.x; t < ntiles; t += gridDim.x) {
        const int i = (t << 8) + tid;
        const bool live = (i < total);
        float px = 0.f, py = 0.f, pz = 0.f;
        int id = -1;
        if (live) {
            float4 e = g_list[i];
            px = e.x; py = e.y; pz = e.z;
            id = __float_as_int(e.w);
        }
        ids_s[tid] = id;
        {
            const uint32_t ro = (uint32_t)tid * A_STRIDE;
            #pragma unroll
            for (int k = 0; k < HDIM; k += 2) {
                float a0 = fmaf(px, W1s[k],     fmaf(py, W1s[HDIM + k],     fmaf(pz, W1s[2 * HDIM + k],     b1s[k])));
                float a1 = fmaf(px, W1s[k + 1], fmaf(py, W1s[HDIM + k + 1], fmaf(pz, W1s[2 * HDIM + k + 1], b1s[k + 1])));
                a0 = fmaxf(a0, 0.0f);
                a1 = fmaxf(a1, 0.0f);
                uint32_t hp; BF16X2(hp, a1, a0);
                float hf0 = __uint_as_float(hp << 16);
                float hf1 = __uint_as_float(hp & 0xffff0000u);
                uint32_t lp; BF16X2(lp, a1 - hf1, a0 - hf0);
                *(uint32_t*)(Ahi + ro + k * 2) = hp;
                *(uint32_t*)(Alo + ro + k * 2) = lp;
            }
        }
        __syncthreads();

        float d[2][8][4];
        #pragma unroll
        for (int mt = 0; mt < 2; mt++)
            #pragma unroll
            for (int j = 0; j < 8; j++) {
                d[mt][j][0] = bb[j].x; d[mt][j][1] = bb[j].y;
                d[mt][j][2] = bb[j].x; d[mt][j][3] = bb[j].y;
            }

        #pragma unroll
        for (int kc = 0; kc < 4; kc++) {
            const int kb = kc * 16;
            uint32_t ah[2][4], al[2][4];
            #pragma unroll
            for (int mt = 0; mt < 2; mt++) {
                const int rb = w * 32 + mt * 16 + g;
                const char* ph = Ahi + rb * A_STRIDE + (kb + 2 * tg) * 2;
                const char* pl = Alo + rb * A_STRIDE + (kb + 2 * tg) * 2;
                ah[mt][0] = *(const uint32_t*)(ph);
                ah[mt][1] = *(const uint32_t*)(ph + 8 * A_STRIDE);
                ah[mt][2] = *(const uint32_t*)(ph + 16);
                ah[mt][3] = *(const uint32_t*)(ph + 8 * A_STRIDE + 16);
                al[mt][0] = *(const uint32_t*)(pl);
                al[mt][1] = *(const uint32_t*)(pl + 8 * A_STRIDE);
                al[mt][2] = *(const uint32_t*)(pl + 16);
                al[mt][3] = *(const uint32_t*)(pl + 8 * A_STRIDE + 16);
            }
            #pragma unroll
            for (int j = 0; j < 8; j++) {
                const char* pb = Bhi + (8 * j + g) * B_STRIDE + (kb + 2 * tg) * 2;
                const char* ql = Blo + (8 * j + g) * B_STRIDE + (kb + 2 * tg) * 2;
                uint32_t bh0 = *(const uint32_t*)(pb);
                uint32_t bh1 = *(const uint32_t*)(pb + 16);
                uint32_t bl0 = *(const uint32_t*)(ql);
                uint32_t bl1 = *(const uint32_t*)(ql + 16);
                mma16816(d[0][j], ah[0], bh0, bh1);
                mma16816(d[1][j], ah[1], bh0, bh1);
                mma16816(d[0][j], al[0], bh0, bh1);
                mma16816(d[1][j], al[1], bh0, bh1);
                mma16816(d[0][j], ah[0], bl0, bl1);
                mma16816(d[1][j], ah[1], bl0, bl1);
            }
        }

        float pr[4][4];
        #pragma unroll
        for (int q = 0; q < 4; q++) {
            pr[q][0] = 0.f; pr[q][1] = 0.f; pr[q][2] = 0.f; pr[q][3] = 0.f;
        }
        #pragma unroll
        for (int mt = 0; mt < 2; mt++) {
            #pragma unroll
            for (int j = 0; j < 8; j++) {
                float4 wl = Wos[8 * j + 2 * tg];
                float4 wh = Wos[8 * j + 2 * tg + 1];
                float h0 = fmaxf(d[mt][j][0], 0.f);
                float h1 = fmaxf(d[mt][j][1], 0.f);
                float h2 = fmaxf(d[mt][j][2], 0.f);
                float h3 = fmaxf(d[mt][j][3], 0.f);
                pr[2 * mt][0] = fmaf(h0, wl.x, fmaf(h1, wh.x, pr[2 * mt][0]));
                pr[2 * mt][1] = fmaf(h0, wl.y, fmaf(h1, wh.y, pr[2 * mt][1]));
                pr[2 * mt][2] = fmaf(h0, wl.z, fmaf(h1, wh.z, pr[2 * mt][2]));
                pr[2 * mt][3] = fmaf(h0, wl.w, fmaf(h1, wh.w, pr[2 * mt][3]));
                pr[2 * mt + 1][0] = fmaf(h2, wl.x, fmaf(h3, wh.x, pr[2 * mt + 1][0]));
                pr[2 * mt + 1][1] = fmaf(h2, wl.y, fmaf(h3, wh.y, pr[2 * mt + 1][1]));
                pr[2 * mt + 1][2] = fmaf(h2, wl.z, fmaf(h3, wh.z, pr[2 * mt + 1][2]));
                pr[2 * mt + 1][3] = fmaf(h2, wl.w, fmaf(h3, wh.w, pr[2 * mt + 1][3]));
            }
        }
        #pragma unroll
        for (int q = 0; q < 4; q++) {
            #pragma unroll
            for (int v = 0; v < 4; v++) {
                float val = pr[q][v];
                val += __shfl_down_sync(0xffffffffu, val, 2, 4);
                val += __shfl_down_sync(0xffffffffu, val, 1, 4);
                pr[q][v] = val;
            }
        }
        if (tg == 0) {
            const int rows[4] = { w * 32 + g, w * 32 + g + 8,
                                  w * 32 + 16 + g, w * 32 + 24 + g };
            #pragma unroll
            for (int q = 0; q < 4; q++) {
                int id2 = ids_s[rows[q]];
                if (id2 >= 0) {
                    float4 outv;
                    outv.x = 1.0f / (1.0f + __expf(-(pr[q][0] + bias4[0])));
                    outv.y = 1.0f / (1.0f + __expf(-(pr[q][1] + bias4[1])));
                    outv.z = 1.0f / (1.0f + __expf(-(pr[q][2] + bias4[2])));
                    outv.w = pr[q][3] + bias4[3];
                    g_rgbsig[id2] = outv;
                }
            }
        }
        __syncthreads();
    }
}

// ============================================================
// K3: per-ray composite, 4 rays per 512-thread CTA
//     also resets g_count for the next graph replay
// ============================================================
__global__ __launch_bounds__(512) void k3_composite(
    const float* __restrict__ near_, const float* __restrict__ far_,
    float* __restrict__ out, int N)
{
    __shared__ float wtot[4][4];
    __shared__ float red[4][12];

    const int tid  = threadIdx.x;
    const int r    = tid >> 7;           // ray in CTA 0..3
    const int rt   = tid & 127;          // thread in ray
    const int lane = tid & 31;
    const int wr   = rt >> 5;            // warp within ray 0..3
    const int n    = blockIdx.x * 4 + r;

    if (blockIdx.x == 0 && tid == 0) g_count = 0;   // reset for next replay

    const bool valid = (n < N);
    float f = 1.0f, alpha = 0.0f;
    float4 rs = make_float4(0.f, 0.f, 0.f, 0.f);
    float step = 0.f;
    bool mask = false;

    if (valid) {
        step = __fmul_rn(__fsub_rn(far_[n], near_[n]), 0.0078125f);
        const unsigned bal = g_maskbits[n * 4 + wr];
        mask = (bal >> lane) & 1u;
        rs = g_rgbsig[n * NSAMP + rt];
        if (mask) {
            float tau = fmaxf(rs.w, 0.0f) * step;
            alpha = 1.0f - __expf(-tau);
        }
        f = 1.0f - alpha + 1e-10f;
    }

    float scan = f;
    #pragma unroll
    for (int off = 1; off < 32; off <<= 1) {
        float v = __shfl_up_sync(0xffffffffu, scan, off);
        if (lane >= off) scan *= v;
    }
    if (lane == 31) wtot[r][wr] = scan;
    __syncthreads();
    float prefix = 1.0f;
    #pragma unroll
    for (int i = 0; i < 4; i++) if (i < wr) prefix *= wtot[r][i];

    float excl = __shfl_up_sync(0xffffffffu, scan, 1);
    if (lane == 0) excl = 1.0f;
    float Tprev = excl * prefix;
    float wgt = alpha * Tprev;

    float c0 = 0.f, c1 = 0.f, c2 = 0.f;
    if (mask) {
        c0 = wgt * rs.x;
        c1 = wgt * rs.y;
        c2 = wgt * rs.z;
    }
    #pragma unroll
    for (int off = 16; off > 0; off >>= 1) {
        c0 += __shfl_down_sync(0xffffffffu, c0, off);
        c1 += __shfl_down_sync(0xffffffffu, c1, off);
        c2 += __shfl_down_sync(0xffffffffu, c2, off);
    }
    if (lane == 0) {
        red[r][wr * 3 + 0] = c0;
        red[r][wr * 3 + 1] = c1;
        red[r][wr * 3 + 2] = c2;
    }
    __syncthreads();
    if (rt == 0 && valid) {
        float nohit = wtot[r][0] * wtot[r][1] * wtot[r][2] * wtot[r][3];
        out[n * 3 + 0] = red[r][0] + red[r][3] + red[r][6] + red[r][9]  + nohit;
        out[n * 3 + 1] = red[r][1] + red[r][4] + red[r][7] + red[r][10] + nohit;
        out[n * 3 + 2] = red[r][2] + red[r][5] + red[r][8] + red[r][11] + nohit;
    }
}

extern "C" void kernel_launch(void* const* d_in, const int* in_sizes, int n_in,
                              void* d_out, int out_size) {
    const float* rays_o  = (const float*)d_in[0];
    const float* rays_d  = (const float*)d_in[1];
    const float* near_   = (const float*)d_in[2];
    const float* far_    = (const float*)d_in[3];
    const float* jitter  = (const float*)d_in[4];
    const float* density = (const float*)d_in[5];
    const float* W1   = (const float*)d_in[6];
    const float* b1   = (const float*)d_in[7];
    const float* W2   = (const float*)d_in[8];
    const float* b2   = (const float*)d_in[9];
    const float* Wsig = (const float*)d_in[10];
    const float* bsig = (const float*)d_in[11];
    const float* Wrgb = (const float*)d_in[12];
    const float* brgb = (const float*)d_in[13];
    float* out = (float*)d_out;

    const int N = in_sizes[2];

    cudaFuncSetAttribute(k2_mlp, cudaFuncAttributeMaxDynamicSharedMemorySize, DYN_SMEM);

    // g_count starts 0 (static init) and is reset by k3 each run — no memset node
    k1_sample<<<(N + 3) / 4, 512>>>(rays_o, rays_d, near_, far_, jitter, density, N);
    k2_mlp<<<296, 256, DYN_SMEM>>>(W1, b1, W2, b2, Wsig, bsig, Wrgb, brgb);
    k3_composite<<<(N + 3) / 4, 512>>>(near_, far_, out, N);
}